// round 3
// baseline (speedup 1.0000x reference)
#include <cuda_runtime.h>
#include <math.h>

// Problem constants (fixed shapes from reference setup_inputs)
constexpr int B  = 8;
constexpr int H  = 384;
constexpr int W  = 512;
constexpr int HW = H * W;            // 196608
constexpr int NPIX = B * HW;         // 1572864
constexpr int N2 = B * 2 * HW;       // flow-sized
constexpr int N3 = B * 3 * HW;       // img-sized

constexpr int TPB = 256;
constexpr int NBLK = NPIX / TPB;     // 6144 (NPIX divisible by 256)

// 5-tap gradient filter coefficients (center tap is 0)
__device__ __constant__ float KC0 = -1.0f / 12.0f;
__device__ __constant__ float KC1 =  2.0f / 3.0f;
__device__ __constant__ float KC3 = -2.0f / 3.0f;
__device__ __constant__ float KC4 =  1.0f / 12.0f;

// Scratch (static device globals — no runtime allocation)
__device__ float g_flow[2][N2];      // [0]=flowf, [1]=flowb
__device__ float g_res [2][N3];      // warp residual img_a - warp(img_b) per direction
__device__ float g_mask[2][NPIX];    // border*occ mask per direction
__device__ float g_acc [3];          // [0]=energy sum, [1]=raw logvar sum, [2]=epe sum

__device__ __forceinline__ float sigm(float x) {
    return 1.0f / (1.0f + __expf(-x));
}

__device__ __forceinline__ float blockReduceSum(float v) {
    __shared__ float s[32];
    int lane = threadIdx.x & 31;
    int wid  = threadIdx.x >> 5;
    #pragma unroll
    for (int o = 16; o; o >>= 1) v += __shfl_down_sync(0xffffffffu, v, o);
    if (lane == 0) s[wid] = v;
    __syncthreads();
    v = 0.0f;
    if (wid == 0) {
        int nw = blockDim.x >> 5;
        v = (lane < nw) ? s[lane] : 0.0f;
        #pragma unroll
        for (int o = 16; o; o >>= 1) v += __shfl_down_sync(0xffffffffu, v, o);
    }
    return v;
}

__global__ void k_zero() {
    if (threadIdx.x < 3) g_acc[threadIdx.x] = 0.0f;
}

// Reparameterize flows, accumulate entropy raw-sum and EPE sum.
__global__ void __launch_bounds__(TPB) k_flow(
    const float* __restrict__ mf, const float* __restrict__ lvf,
    const float* __restrict__ mb, const float* __restrict__ lvb,
    const float* __restrict__ tgt,
    const float* __restrict__ nf, const float* __restrict__ nb)
{
    int p = blockIdx.x * blockDim.x + threadIdx.x;   // pixel id in [0, NPIX)
    int b  = p / HW;
    int rr = p - b * HW;
    int i0 = (b * 2 + 0) * HW + rr;
    int i1 = i0 + HW;

    float mf0 = mf[i0], mf1 = mf[i1];
    float lf0 = lvf[i0], lf1 = lvf[i1];
    float mb0 = mb[i0], mb1 = mb[i1];
    float lb0 = lvb[i0], lb1 = lvb[i1];
    float t0  = tgt[i0], t1  = tgt[i1];
    float nf0 = nf[i0], nf1 = nf[i1];
    float nb0 = nb[i0], nb1 = nb[i1];

    g_flow[0][i0] = mf0 + expf(lf0 * 0.5f) * nf0;
    g_flow[0][i1] = mf1 + expf(lf1 * 0.5f) * nf1;
    g_flow[1][i0] = mb0 + expf(lb0 * 0.5f) * nb0;
    g_flow[1][i1] = mb1 + expf(lb1 * 0.5f) * nb1;

    float ent = lf0 + lf1 + lb0 + lb1;
    float d0 = mf0 - t0, d1 = mf1 - t1;
    float epe = sqrtf(d0 * d0 + d1 * d1);

    float es = blockReduceSum(ent);
    __syncthreads();
    float ps = blockReduceSum(epe);
    if (threadIdx.x == 0) {
        atomicAdd(&g_acc[1], es);
        atomicAdd(&g_acc[2], ps);
    }
}

// Per-direction main energy: border+occ mask, warps, data/fb/smooth terms.
// dir=0: flowA=flowf, flowB=flowb, imgA=img1, imgB=img2
__global__ void __launch_bounds__(TPB) k_dir(
    int dir,
    const float* __restrict__ imgA, const float* __restrict__ imgB)
{
    int p = blockIdx.x * blockDim.x + threadIdx.x;
    int b  = p / HW;
    int rr = p - b * HW;
    int y  = rr / W;
    int x  = rr - y * W;

    const float* __restrict__ fA = g_flow[dir];
    const float* __restrict__ fB = g_flow[dir ^ 1];
    float* __restrict__ res  = g_res[dir];
    float* __restrict__ mout = g_mask[dir];

    int baseF0 = (b * 2) * HW;          // flow ch0 base for this batch
    int baseF1 = baseF0 + HW;
    int baseI  = (b * 3) * HW;          // img ch0 base

    float fax = fA[baseF0 + rr];
    float fay = fA[baseF1 + rr];

    float Xp = (float)x + fax;
    float Yp = (float)y + fay;

    // Border mask
    float mx = sigm(Xp + 0.5f) * (1.0f - sigm(Xp - ((float)W - 0.5f)));
    float my = sigm(Yp + 0.5f) * (1.0f - sigm(Yp - ((float)H - 0.5f)));
    float border = mx * my;

    // Bilinear setup
    float x0f = floorf(Xp), y0f = floorf(Yp);
    float wx = Xp - x0f,    wy = Yp - y0f;
    int x0 = (int)x0f, y0 = (int)y0f;
    bool vx0 = (x0 >= 0)     && (x0 <= W - 1);
    bool vx1 = (x0 + 1 >= 0) && (x0 + 1 <= W - 1);
    bool vy0 = (y0 >= 0)     && (y0 <= H - 1);
    bool vy1 = (y0 + 1 >= 0) && (y0 + 1 <= H - 1);
    float w00 = (1.0f - wx) * (1.0f - wy) * (float)(vx0 && vy0);
    float w10 = wx * (1.0f - wy)          * (float)(vx1 && vy0);
    float w01 = (1.0f - wx) * wy          * (float)(vx0 && vy1);
    float w11 = wx * wy                    * (float)(vx1 && vy1);
    int cx0 = min(max(x0, 0), W - 1);
    int cx1 = min(max(x0 + 1, 0), W - 1);
    int cy0 = min(max(y0, 0), H - 1);
    int cy1 = min(max(y0 + 1, 0), H - 1);
    int i00 = cy0 * W + cx0;
    int i10 = cy0 * W + cx1;
    int i01 = cy1 * W + cx0;
    int i11 = cy1 * W + cx1;

    // Warp opposite flow
    const float* fB0 = fB + baseF0;
    const float* fB1 = fB + baseF1;
    float fbw0 = w00 * fB0[i00] + w10 * fB0[i10] + w01 * fB0[i01] + w11 * fB0[i11];
    float fbw1 = w00 * fB1[i00] + w10 * fB1[i10] + w01 * fB1[i01] + w11 * fB1[i11];

    float mag  = fax * fax + fay * fay + fbw0 * fbw0 + fbw1 * fbw1;
    float dfx  = fax + fbw0;
    float dfy  = fay + fbw1;
    float D    = dfx * dfx + dfy * dfy;
    float occ  = 1.0f - sigm(D - (0.01f * mag + 0.5f));
    float mask = border * occ;
    mout[p] = mask;

    // Warp image, residual
    float A = 0.0f;
    #pragma unroll
    for (int c = 0; c < 3; ++c) {
        const float* ib = imgB + baseI + c * HW;
        float wv = w00 * ib[i00] + w10 * ib[i10] + w01 * ib[i01] + w11 * ib[i11];
        float rc = imgA[baseI + c * HW + rr] - wv;
        res[baseI + c * HW + rr] = rc;
        A += rc * rc;
    }

    // Smoothness (forward diffs, padded with zeros at last col/row)
    float dx2 = 0.0f;
    if (x < W - 1) {
        float d0 = fA[baseF0 + rr + 1] - fax;
        float d1 = fA[baseF1 + rr + 1] - fay;
        dx2 = d0 * d0 + d1 * d1;
    }
    float dy2 = 0.0f;
    if (y < H - 1) {
        float d0 = fA[baseF0 + rr + W] - fax;
        float d1 = fA[baseF1 + rr + W] - fay;
        dy2 = d0 * d0 + d1 * d1;
    }

    float e = (1.0f - mask)                       // mask_term
            + sqrtf(A + 1e-5f) * mask             // data_term
            + sqrtf(dx2 + dy2 + 1e-5f)            // smooth_term
            + sqrtf(D + 1e-5f) * mask;            // fb_part

    float bs = blockReduceSum(e);
    if (threadIdx.x == 0) atomicAdd(&g_acc[0], bs);
}

// Gradient-constancy term: 5-tap stencil (center weight 0) on residual.
__global__ void __launch_bounds__(TPB) k_grad(int dir)
{
    int p = blockIdx.x * blockDim.x + threadIdx.x;
    int b  = p / HW;
    int rr = p - b * HW;
    int y  = rr / W;
    int x  = rr - y * W;

    const float* __restrict__ res = g_res[dir];
    int baseI = (b * 3) * HW;

    bool xm2 = (x >= 2), xm1 = (x >= 1), xp1 = (x <= W - 2), xp2 = (x <= W - 3);
    bool ym2 = (y >= 2), ym1 = (y >= 1), yp1 = (y <= H - 2), yp2 = (y <= H - 3);

    float Ct = 0.0f;
    #pragma unroll
    for (int c = 0; c < 3; ++c) {
        const float* rb = res + baseI + c * HW;
        float gx = 0.0f, gy = 0.0f;
        if (xm2) gx += KC0 * rb[rr - 2];
        if (xm1) gx += KC1 * rb[rr - 1];
        if (xp1) gx += KC3 * rb[rr + 1];
        if (xp2) gx += KC4 * rb[rr + 2];
        if (ym2) gy += KC0 * rb[rr - 2 * W];
        if (ym1) gy += KC1 * rb[rr - W];
        if (yp1) gy += KC3 * rb[rr + W];
        if (yp2) gy += KC4 * rb[rr + 2 * W];
        Ct += gx * gx + gy * gy;
    }

    float e = sqrtf(Ct + 1e-5f) * g_mask[dir][p];

    float bs = blockReduceSum(e);
    if (threadIdx.x == 0) atomicAdd(&g_acc[0], bs);
}

__global__ void k_final(float* __restrict__ out)
{
    float energy  = g_acc[0] * (1.0f / (float)B);
    float entropy = g_acc[1] * (1.0f / (2.0f * (float)B));
    out[0] = energy - entropy;                       // elbo
    out[1] = g_acc[2] * (1.0f / (float)NPIX);        // epe
}

extern "C" void kernel_launch(void* const* d_in, const int* in_sizes, int n_in,
                              void* d_out, int out_size)
{
    const float* meanf   = (const float*)d_in[0];
    const float* logvarf = (const float*)d_in[1];
    const float* meanb   = (const float*)d_in[2];
    const float* logvarb = (const float*)d_in[3];
    const float* img1    = (const float*)d_in[4];
    const float* img2    = (const float*)d_in[5];
    const float* target  = (const float*)d_in[6];
    const float* noise_f = (const float*)d_in[7];
    const float* noise_b = (const float*)d_in[8];
    float* out = (float*)d_out;

    k_zero<<<1, 32>>>();
    k_flow<<<NBLK, TPB>>>(meanf, logvarf, meanb, logvarb, target, noise_f, noise_b);
    k_dir<<<NBLK, TPB>>>(0, img1, img2);
    k_dir<<<NBLK, TPB>>>(1, img2, img1);
    k_grad<<<NBLK, TPB>>>(0);
    k_grad<<<NBLK, TPB>>>(1);
    k_final<<<1, 1>>>(out);
}

// round 7
// speedup vs baseline: 1.3232x; 1.3232x over previous
#include <cuda_runtime.h>
#include <math.h>

// Fixed problem shapes
constexpr int B  = 8;
constexpr int H  = 384;
constexpr int W  = 512;
constexpr int HW = H * W;            // 196608
constexpr int NPIX = B * HW;         // 1572864
constexpr int N2 = B * 2 * HW;
constexpr int N3 = B * 3 * HW;

constexpr int TPB = 256;
constexpr int NQUAD = NPIX / 4;      // 393216
constexpr int NBLKQ = NQUAD / TPB;   // 1536

// 5-tap gradient filter coefficients (center tap is 0)
constexpr float KC0 = -1.0f / 12.0f;
constexpr float KC1 =  2.0f / 3.0f;
constexpr float KC3 = -2.0f / 3.0f;
constexpr float KC4 =  1.0f / 12.0f;

// Scratch (static device globals)
__device__ float g_flow[2][N2];      // [0]=flowf, [1]=flowb
__device__ float g_res [2][N3];      // warp residual per direction
__device__ float g_mask[2][NPIX];    // border*occ mask per direction
__device__ float g_acc [3];          // [0]=energy, [1]=logvar raw sum, [2]=epe sum

__device__ __forceinline__ float sigm(float x) {
    return 1.0f / (1.0f + __expf(-x));
}

__device__ __forceinline__ float4 ld4(const float* p) {
    return *reinterpret_cast<const float4*>(p);
}
__device__ __forceinline__ void st4(float* p, float4 v) {
    *reinterpret_cast<float4*>(p) = v;
}
__device__ __forceinline__ void unpack(float4 v, float* a) {
    a[0] = v.x; a[1] = v.y; a[2] = v.z; a[3] = v.w;
}

__device__ __forceinline__ float blockReduceSum(float v) {
    __shared__ float s[32];
    int lane = threadIdx.x & 31;
    int wid  = threadIdx.x >> 5;
    #pragma unroll
    for (int o = 16; o; o >>= 1) v += __shfl_down_sync(0xffffffffu, v, o);
    if (lane == 0) s[wid] = v;
    __syncthreads();
    v = 0.0f;
    if (wid == 0) {
        v = (lane < (TPB >> 5)) ? s[lane] : 0.0f;
        #pragma unroll
        for (int o = 16; o; o >>= 1) v += __shfl_down_sync(0xffffffffu, v, o);
    }
    return v;
}

__global__ void k_zero() {
    if (threadIdx.x < 3) g_acc[threadIdx.x] = 0.0f;
}

// Reparameterize flows (float4), accumulate entropy raw-sum and EPE sum.
__global__ void __launch_bounds__(TPB) k_flow(
    const float* __restrict__ mf, const float* __restrict__ lvf,
    const float* __restrict__ mb, const float* __restrict__ lvb,
    const float* __restrict__ tgt,
    const float* __restrict__ nf, const float* __restrict__ nb)
{
    int q = blockIdx.x * blockDim.x + threadIdx.x;   // quad id in [0, NQUAD)
    int p = q * 4;
    int b  = p / HW;
    int rr = p - b * HW;
    int i0 = (b * 2) * HW + rr;
    int i1 = i0 + HW;

    float mf0[4], mf1[4], lf0[4], lf1[4], mb0[4], mb1[4], lb0[4], lb1[4];
    float t0[4], t1[4], nf0[4], nf1[4], nb0[4], nb1[4];
    unpack(ld4(mf  + i0), mf0); unpack(ld4(mf  + i1), mf1);
    unpack(ld4(lvf + i0), lf0); unpack(ld4(lvf + i1), lf1);
    unpack(ld4(mb  + i0), mb0); unpack(ld4(mb  + i1), mb1);
    unpack(ld4(lvb + i0), lb0); unpack(ld4(lvb + i1), lb1);
    unpack(ld4(tgt + i0), t0);  unpack(ld4(tgt + i1), t1);
    unpack(ld4(nf  + i0), nf0); unpack(ld4(nf  + i1), nf1);
    unpack(ld4(nb  + i0), nb0); unpack(ld4(nb  + i1), nb1);

    float ff0[4], ff1[4], fb0[4], fb1[4];
    float ent = 0.0f, epe = 0.0f;
    #pragma unroll
    for (int i = 0; i < 4; ++i) {
        ff0[i] = mf0[i] + __expf(lf0[i] * 0.5f) * nf0[i];
        ff1[i] = mf1[i] + __expf(lf1[i] * 0.5f) * nf1[i];
        fb0[i] = mb0[i] + __expf(lb0[i] * 0.5f) * nb0[i];
        fb1[i] = mb1[i] + __expf(lb1[i] * 0.5f) * nb1[i];
        ent += lf0[i] + lf1[i] + lb0[i] + lb1[i];
        float d0 = mf0[i] - t0[i], d1 = mf1[i] - t1[i];
        epe += sqrtf(d0 * d0 + d1 * d1);
    }
    st4(&g_flow[0][i0], make_float4(ff0[0], ff0[1], ff0[2], ff0[3]));
    st4(&g_flow[0][i1], make_float4(ff1[0], ff1[1], ff1[2], ff1[3]));
    st4(&g_flow[1][i0], make_float4(fb0[0], fb0[1], fb0[2], fb0[3]));
    st4(&g_flow[1][i1], make_float4(fb1[0], fb1[1], fb1[2], fb1[3]));

    float es = blockReduceSum(ent);
    __syncthreads();
    float ps = blockReduceSum(epe);
    if (threadIdx.x == 0) {
        atomicAdd(&g_acc[1], es);
        atomicAdd(&g_acc[2], ps);
    }
}

// Per-direction main energy (both directions via blockIdx.y), 4 pixels/thread.
__global__ void __launch_bounds__(TPB) k_dir(
    const float* __restrict__ img1, const float* __restrict__ img2)
{
    int dir = blockIdx.y;
    const float* __restrict__ imgA = dir ? img2 : img1;
    const float* __restrict__ imgB = dir ? img1 : img2;

    int q = blockIdx.x * blockDim.x + threadIdx.x;
    int p = q * 4;
    int b  = p / HW;
    int rr = p - b * HW;
    int y  = rr / W;
    int x  = rr - y * W;   // multiple of 4

    const float* __restrict__ fA = g_flow[dir];
    const float* __restrict__ fB = g_flow[dir ^ 1];
    float* __restrict__ res  = g_res[dir];
    float* __restrict__ mout = g_mask[dir];

    int baseF0 = (b * 2) * HW;
    int baseF1 = baseF0 + HW;
    int baseI  = (b * 3) * HW;

    float fax[4], fay[4];
    unpack(ld4(fA + baseF0 + rr), fax);
    unpack(ld4(fA + baseF1 + rr), fay);

    // imgA channels
    float ia[3][4];
    #pragma unroll
    for (int c = 0; c < 3; ++c) unpack(ld4(imgA + baseI + c * HW + rr), ia[c]);

    const float* fB0 = fB + baseF0;
    const float* fB1 = fB + baseF1;
    const float* ib0 = imgB + baseI;
    const float* ib1 = ib0 + HW;
    const float* ib2 = ib1 + HW;

    float maskv[4], Dv[4], Av[4];
    float rc[3][4];

    #pragma unroll
    for (int i = 0; i < 4; ++i) {
        float Xp = (float)(x + i) + fax[i];
        float Yp = (float)y + fay[i];

        float mx = sigm(Xp + 0.5f) * (1.0f - sigm(Xp - ((float)W - 0.5f)));
        float my = sigm(Yp + 0.5f) * (1.0f - sigm(Yp - ((float)H - 0.5f)));
        float border = mx * my;

        float x0f = floorf(Xp), y0f = floorf(Yp);
        float wx = Xp - x0f,    wy = Yp - y0f;
        int x0 = (int)x0f, y0 = (int)y0f;
        bool vx0 = (x0 >= 0)     && (x0 <= W - 1);
        bool vx1 = (x0 + 1 >= 0) && (x0 + 1 <= W - 1);
        bool vy0 = (y0 >= 0)     && (y0 <= H - 1);
        bool vy1 = (y0 + 1 >= 0) && (y0 + 1 <= H - 1);
        float w00 = (1.0f - wx) * (1.0f - wy) * (float)(vx0 && vy0);
        float w10 = wx * (1.0f - wy)          * (float)(vx1 && vy0);
        float w01 = (1.0f - wx) * wy          * (float)(vx0 && vy1);
        float w11 = wx * wy                    * (float)(vx1 && vy1);
        int cx0 = min(max(x0, 0), W - 1);
        int cx1 = min(max(x0 + 1, 0), W - 1);
        int cy0 = min(max(y0, 0), H - 1);
        int cy1 = min(max(y0 + 1, 0), H - 1);
        int i00 = cy0 * W + cx0;
        int i10 = cy0 * W + cx1;
        int i01 = cy1 * W + cx0;
        int i11 = cy1 * W + cx1;

        float fbw0 = w00 * fB0[i00] + w10 * fB0[i10] + w01 * fB0[i01] + w11 * fB0[i11];
        float fbw1 = w00 * fB1[i00] + w10 * fB1[i10] + w01 * fB1[i01] + w11 * fB1[i11];

        float mag = fax[i] * fax[i] + fay[i] * fay[i] + fbw0 * fbw0 + fbw1 * fbw1;
        float dfx = fax[i] + fbw0;
        float dfy = fay[i] + fbw1;
        float D   = dfx * dfx + dfy * dfy;
        float occ = 1.0f - sigm(D - (0.01f * mag + 0.5f));
        maskv[i] = border * occ;
        Dv[i] = D;

        float w0 = w00 * ib0[i00] + w10 * ib0[i10] + w01 * ib0[i01] + w11 * ib0[i11];
        float w1 = w00 * ib1[i00] + w10 * ib1[i10] + w01 * ib1[i01] + w11 * ib1[i11];
        float w2 = w00 * ib2[i00] + w10 * ib2[i10] + w01 * ib2[i01] + w11 * ib2[i11];
        rc[0][i] = ia[0][i] - w0;
        rc[1][i] = ia[1][i] - w1;
        rc[2][i] = ia[2][i] - w2;
        Av[i] = rc[0][i] * rc[0][i] + rc[1][i] * rc[1][i] + rc[2][i] * rc[2][i];
    }

    // Stores
    st4(&mout[p], make_float4(maskv[0], maskv[1], maskv[2], maskv[3]));
    #pragma unroll
    for (int c = 0; c < 3; ++c)
        st4(&res[baseI + c * HW + rr], make_float4(rc[c][0], rc[c][1], rc[c][2], rc[c][3]));

    // Smoothness: need right-neighbor flow (x+4) and next-row flow
    bool hasR = (x + 4) < W;
    float faxn = hasR ? fA[baseF0 + rr + 4] : 0.0f;
    float fayn = hasR ? fA[baseF1 + rr + 4] : 0.0f;
    bool hasD = (y + 1) < H;
    float faxd[4] = {0, 0, 0, 0}, fayd[4] = {0, 0, 0, 0};
    if (hasD) {
        unpack(ld4(fA + baseF0 + rr + W), faxd);
        unpack(ld4(fA + baseF1 + rr + W), fayd);
    }

    float e = 0.0f;
    #pragma unroll
    for (int i = 0; i < 4; ++i) {
        float dx2 = 0.0f;
        if (x + i < W - 1) {
            float nx = (i < 3) ? fax[i + 1] : faxn;
            float ny = (i < 3) ? fay[i + 1] : fayn;
            float d0 = nx - fax[i];
            float d1 = ny - fay[i];
            dx2 = d0 * d0 + d1 * d1;
        }
        float dy2 = 0.0f;
        if (hasD) {
            float d0 = faxd[i] - fax[i];
            float d1 = fayd[i] - fay[i];
            dy2 = d0 * d0 + d1 * d1;
        }
        e += (1.0f - maskv[i])
           + sqrtf(Av[i] + 1e-5f) * maskv[i]
           + sqrtf(dx2 + dy2 + 1e-5f)
           + sqrtf(Dv[i] + 1e-5f) * maskv[i];
    }

    float bs = blockReduceSum(e);
    if (threadIdx.x == 0) atomicAdd(&g_acc[0], bs);
}

// Gradient-constancy term: 5-tap stencil on residual, 4 pixels/thread, both dirs.
__global__ void __launch_bounds__(TPB) k_grad(int /*unused*/)
{
    int dir = blockIdx.y;
    int q = blockIdx.x * blockDim.x + threadIdx.x;
    int p = q * 4;
    int b  = p / HW;
    int rr = p - b * HW;
    int y  = rr / W;
    int x  = rr - y * W;

    const float* __restrict__ res = g_res[dir];
    int baseI = (b * 3) * HW;

    bool hasL  = x >= 4;
    bool hasR  = (x + 4) < W;
    bool hYm2 = y >= 2, hYm1 = y >= 1, hYp1 = y < H - 1, hYp2 = y < H - 2;

    float Ct[4] = {0, 0, 0, 0};
    #pragma unroll
    for (int c = 0; c < 3; ++c) {
        const float* rb = res + baseI + c * HW + rr;
        float a[12];
        if (hasL) unpack(ld4(rb - 4), &a[0]);
        else { a[0] = a[1] = a[2] = a[3] = 0.0f; }
        unpack(ld4(rb), &a[4]);
        if (hasR) unpack(ld4(rb + 4), &a[8]);
        else { a[8] = a[9] = a[10] = a[11] = 0.0f; }

        float ym2[4] = {0,0,0,0}, ym1[4] = {0,0,0,0}, yp1[4] = {0,0,0,0}, yp2[4] = {0,0,0,0};
        if (hYm2) unpack(ld4(rb - 2 * W), ym2);
        if (hYm1) unpack(ld4(rb - W), ym1);
        if (hYp1) unpack(ld4(rb + W), yp1);
        if (hYp2) unpack(ld4(rb + 2 * W), yp2);

        #pragma unroll
        for (int i = 0; i < 4; ++i) {
            float gx = KC0 * a[i + 2] + KC1 * a[i + 3] + KC3 * a[i + 5] + KC4 * a[i + 6];
            float gy = KC0 * ym2[i] + KC1 * ym1[i] + KC3 * yp1[i] + KC4 * yp2[i];
            Ct[i] += gx * gx + gy * gy;
        }
    }

    float m[4];
    unpack(ld4(&g_mask[dir][p]), m);
    float e = 0.0f;
    #pragma unroll
    for (int i = 0; i < 4; ++i) e += sqrtf(Ct[i] + 1e-5f) * m[i];

    float bs = blockReduceSum(e);
    if (threadIdx.x == 0) atomicAdd(&g_acc[0], bs);
}

__global__ void k_final(float* __restrict__ out)
{
    float energy  = g_acc[0] * (1.0f / (float)B);
    float entropy = g_acc[1] * (1.0f / (2.0f * (float)B));
    out[0] = energy - entropy;
    out[1] = g_acc[2] * (1.0f / (float)NPIX);
}

extern "C" void kernel_launch(void* const* d_in, const int* in_sizes, int n_in,
                              void* d_out, int out_size)
{
    const float* meanf   = (const float*)d_in[0];
    const float* logvarf = (const float*)d_in[1];
    const float* meanb   = (const float*)d_in[2];
    const float* logvarb = (const float*)d_in[3];
    const float* img1    = (const float*)d_in[4];
    const float* img2    = (const float*)d_in[5];
    const float* target  = (const float*)d_in[6];
    const float* noise_f = (const float*)d_in[7];
    const float* noise_b = (const float*)d_in[8];
    float* out = (float*)d_out;

    dim3 grid2(NBLKQ, 2);

    k_zero<<<1, 32>>>();
    k_flow<<<NBLKQ, TPB>>>(meanf, logvarf, meanb, logvarb, target, noise_f, noise_b);
    k_dir<<<grid2, TPB>>>(img1, img2);
    k_grad<<<grid2, TPB>>>(0);
    k_final<<<1, 1>>>(out);
}